// round 1
// baseline (speedup 1.0000x reference)
#include <cuda_runtime.h>
#include <cstdint>

// Problem shape (fixed): x [4, 2048, 1024] fp32; Wq/Wk/Wv [1024, 1024] fp32.
// out = causal_attention(xWq, xWk, xWv) -> [4, 2048, 1024] fp32.

#define BATCH 4
#define SEQ   2048
#define DMODEL 1024
#define MTOT  (BATCH * SEQ)        // 8192

#define BM 64
#define BN 64
#define BK 16
#define TM 4
#define TN 4
#define NTHREADS 256               // (BM/TM)*(BN/TN)

// Scratch (no cudaMalloc allowed): ~168 MB of __device__ globals.
__device__ float g_Q[MTOT * DMODEL];
__device__ float g_K[MTOT * DMODEL];
__device__ float g_V[MTOT * DMODEL];
__device__ float g_S[BATCH * SEQ * SEQ];

// ---------------------------------------------------------------------------
// Kernel 1: QKV projection.  C = X[8192,1024] @ W[1024,1024], z in {Q,K,V}.
// ---------------------------------------------------------------------------
__global__ __launch_bounds__(NTHREADS) void qkv_kernel(
    const float* __restrict__ x,
    const float* __restrict__ Wq,
    const float* __restrict__ Wk,
    const float* __restrict__ Wv)
{
    const int K = DMODEL, N = DMODEL;
    const float* W = (blockIdx.z == 0) ? Wq : (blockIdx.z == 1) ? Wk : Wv;
    float* C = (blockIdx.z == 0) ? g_Q : (blockIdx.z == 1) ? g_K : g_V;

    __shared__ float As[BK][BM + 4];   // transposed A tile, padded
    __shared__ float Bs[BK][BN + 4];

    const int t  = threadIdx.x;
    const int tx = t & 15;             // 0..15 -> N direction
    const int ty = t >> 4;             // 0..15 -> M direction
    const int rowBase = blockIdx.y * BM;
    const int colBase = blockIdx.x * BN;

    const int aRow  = t >> 2;          // 0..63
    const int aQuad = t & 3;           // 0..3
    const int bRow  = t >> 4;          // 0..15
    const int bQuad = t & 15;          // 0..15

    float acc[TM][TN] = {};

    for (int k0 = 0; k0 < K; k0 += BK) {
        float4 av = *(const float4*)&x[(size_t)(rowBase + aRow) * K + k0 + aQuad * 4];
        As[aQuad * 4 + 0][aRow] = av.x;
        As[aQuad * 4 + 1][aRow] = av.y;
        As[aQuad * 4 + 2][aRow] = av.z;
        As[aQuad * 4 + 3][aRow] = av.w;
        float4 bv = *(const float4*)&W[(size_t)(k0 + bRow) * N + colBase + bQuad * 4];
        *(float4*)&Bs[bRow][bQuad * 4] = bv;
        __syncthreads();
        #pragma unroll
        for (int kk = 0; kk < BK; kk++) {
            float4 a = *(const float4*)&As[kk][ty * 4];
            float4 b = *(const float4*)&Bs[kk][tx * 4];
            float ar[4] = {a.x, a.y, a.z, a.w};
            float br[4] = {b.x, b.y, b.z, b.w};
            #pragma unroll
            for (int i = 0; i < TM; i++)
                #pragma unroll
                for (int j = 0; j < TN; j++)
                    acc[i][j] += ar[i] * br[j];
        }
        __syncthreads();
    }

    #pragma unroll
    for (int i = 0; i < TM; i++) {
        float4 v = make_float4(acc[i][0], acc[i][1], acc[i][2], acc[i][3]);
        *(float4*)&C[(size_t)(rowBase + ty * 4 + i) * N + colBase + tx * 4] = v;
    }
}

// ---------------------------------------------------------------------------
// Kernel 2: S[b] = (Q[b] @ K[b]^T) * scale, only lower-triangle tiles.
// ---------------------------------------------------------------------------
__global__ __launch_bounds__(NTHREADS) void scores_kernel()
{
    const int by = blockIdx.y;   // query tile
    const int bx = blockIdx.x;   // key tile
    if (bx > by) return;         // strictly-above-diagonal tile: never read later
    const int b = blockIdx.z;

    const float* Qb = g_Q + (size_t)b * SEQ * DMODEL;
    const float* Kb = g_K + (size_t)b * SEQ * DMODEL;
    float*       Sb = g_S + (size_t)b * SEQ * SEQ;

    __shared__ float As[BK][BM + 4];
    __shared__ float Bs[BK][BN + 4];

    const int t  = threadIdx.x;
    const int tx = t & 15;
    const int ty = t >> 4;
    const int rowBase = by * BM;
    const int colBase = bx * BN;

    const int aRow  = t >> 2;
    const int aQuad = t & 3;

    float acc[TM][TN] = {};

    for (int k0 = 0; k0 < DMODEL; k0 += BK) {
        float4 av = *(const float4*)&Qb[(size_t)(rowBase + aRow) * DMODEL + k0 + aQuad * 4];
        As[aQuad * 4 + 0][aRow] = av.x;
        As[aQuad * 4 + 1][aRow] = av.y;
        As[aQuad * 4 + 2][aRow] = av.z;
        As[aQuad * 4 + 3][aRow] = av.w;
        float4 bv = *(const float4*)&Kb[(size_t)(colBase + aRow) * DMODEL + k0 + aQuad * 4];
        Bs[aQuad * 4 + 0][aRow] = bv.x;
        Bs[aQuad * 4 + 1][aRow] = bv.y;
        Bs[aQuad * 4 + 2][aRow] = bv.z;
        Bs[aQuad * 4 + 3][aRow] = bv.w;
        __syncthreads();
        #pragma unroll
        for (int kk = 0; kk < BK; kk++) {
            float4 a = *(const float4*)&As[kk][ty * 4];
            float4 b2 = *(const float4*)&Bs[kk][tx * 4];
            float ar[4] = {a.x, a.y, a.z, a.w};
            float br[4] = {b2.x, b2.y, b2.z, b2.w};
            #pragma unroll
            for (int i = 0; i < TM; i++)
                #pragma unroll
                for (int j = 0; j < TN; j++)
                    acc[i][j] += ar[i] * br[j];
        }
        __syncthreads();
    }

    const float scale = 0.03125f;  // 1/sqrt(1024)
    #pragma unroll
    for (int i = 0; i < TM; i++) {
        float4 v = make_float4(acc[i][0] * scale, acc[i][1] * scale,
                               acc[i][2] * scale, acc[i][3] * scale);
        *(float4*)&Sb[(size_t)(rowBase + ty * 4 + i) * SEQ + colBase + tx * 4] = v;
    }
}

// ---------------------------------------------------------------------------
// Kernel 3: causal row softmax in place; zero-fill masked tail of each row.
// ---------------------------------------------------------------------------
__global__ __launch_bounds__(NTHREADS) void softmax_kernel()
{
    __shared__ float buf[SEQ];
    __shared__ float red[8];

    const int row = blockIdx.x;          // 0..8191
    const int b = row >> 11;
    const int q = row & (SEQ - 1);
    float* S = g_S + ((size_t)b * SEQ + q) * SEQ;
    const int L = q + 1;
    const int t = threadIdx.x;

    float mx = -3.402823e38f;
    for (int i = t; i < L; i += NTHREADS) {
        float v = S[i];
        buf[i] = v;
        mx = fmaxf(mx, v);
    }
    #pragma unroll
    for (int o = 16; o; o >>= 1) mx = fmaxf(mx, __shfl_xor_sync(0xFFFFFFFFu, mx, o));
    if ((t & 31) == 0) red[t >> 5] = mx;
    __syncthreads();
    float m = red[0];
    #pragma unroll
    for (int i = 1; i < 8; i++) m = fmaxf(m, red[i]);
    __syncthreads();   // everyone has read red before it is reused

    float sum = 0.0f;
    for (int i = t; i < L; i += NTHREADS) {
        float e = __expf(buf[i] - m);
        buf[i] = e;
        sum += e;
    }
    #pragma unroll
    for (int o = 16; o; o >>= 1) sum += __shfl_xor_sync(0xFFFFFFFFu, sum, o);
    if ((t & 31) == 0) red[t >> 5] = sum;
    __syncthreads();
    float s = 0.0f;
    #pragma unroll
    for (int i = 0; i < 8; i++) s += red[i];
    const float inv = 1.0f / s;

    for (int i = t; i < SEQ; i += NTHREADS)
        S[i] = (i < L) ? buf[i] * inv : 0.0f;
}

// ---------------------------------------------------------------------------
// Kernel 4: O[b] = P[b] @ V[b], K-loop truncated at the causal diagonal.
// ---------------------------------------------------------------------------
__global__ __launch_bounds__(NTHREADS) void pv_kernel(float* __restrict__ out)
{
    const int by = blockIdx.y;   // query tile (0..31)
    const int bx = blockIdx.x;   // d_out tile (0..15)
    const int b = blockIdx.z;

    const float* Pb = g_S + (size_t)b * SEQ * SEQ;
    const float* Vb = g_V + (size_t)b * SEQ * DMODEL;
    float*       Ob = out + (size_t)b * SEQ * DMODEL;

    __shared__ float As[BK][BM + 4];
    __shared__ float Bs[BK][BN + 4];

    const int t  = threadIdx.x;
    const int tx = t & 15;
    const int ty = t >> 4;
    const int rowBase = by * BM;
    const int colBase = bx * BN;

    const int aRow  = t >> 2;
    const int aQuad = t & 3;
    const int bRow  = t >> 4;
    const int bQuad = t & 15;

    const int kmax = (by + 1) * BM;   // keys beyond this are zero-weight

    float acc[TM][TN] = {};

    for (int k0 = 0; k0 < kmax; k0 += BK) {
        float4 av = *(const float4*)&Pb[(size_t)(rowBase + aRow) * SEQ + k0 + aQuad * 4];
        As[aQuad * 4 + 0][aRow] = av.x;
        As[aQuad * 4 + 1][aRow] = av.y;
        As[aQuad * 4 + 2][aRow] = av.z;
        As[aQuad * 4 + 3][aRow] = av.w;
        float4 bv = *(const float4*)&Vb[(size_t)(k0 + bRow) * DMODEL + colBase + bQuad * 4];
        *(float4*)&Bs[bRow][bQuad * 4] = bv;
        __syncthreads();
        #pragma unroll
        for (int kk = 0; kk < BK; kk++) {
            float4 a = *(const float4*)&As[kk][ty * 4];
            float4 b2 = *(const float4*)&Bs[kk][tx * 4];
            float ar[4] = {a.x, a.y, a.z, a.w};
            float br[4] = {b2.x, b2.y, b2.z, b2.w};
            #pragma unroll
            for (int i = 0; i < TM; i++)
                #pragma unroll
                for (int j = 0; j < TN; j++)
                    acc[i][j] += ar[i] * br[j];
        }
        __syncthreads();
    }

    #pragma unroll
    for (int i = 0; i < TM; i++) {
        float4 v = make_float4(acc[i][0], acc[i][1], acc[i][2], acc[i][3]);
        *(float4*)&Ob[(size_t)(rowBase + ty * 4 + i) * DMODEL + colBase + tx * 4] = v;
    }
}

// ---------------------------------------------------------------------------
extern "C" void kernel_launch(void* const* d_in, const int* in_sizes, int n_in,
                              void* d_out, int out_size)
{
    const float* x  = (const float*)d_in[0];
    const float* Wq = (const float*)d_in[1];
    const float* Wk = (const float*)d_in[2];
    const float* Wv = (const float*)d_in[3];
    float* out = (float*)d_out;

    qkv_kernel<<<dim3(DMODEL / BN, MTOT / BM, 3), NTHREADS>>>(x, Wq, Wk, Wv);
    scores_kernel<<<dim3(SEQ / BN, SEQ / BM, BATCH), NTHREADS>>>();
    softmax_kernel<<<MTOT, NTHREADS>>>();
    pv_kernel<<<dim3(DMODEL / BN, SEQ / BM, BATCH), NTHREADS>>>(out);
}

// round 2
// speedup vs baseline: 2.8564x; 2.8564x over previous
#include <cuda_runtime.h>
#include <cstdint>

// x [4, 2048, 1024] fp32; Wq/Wk/Wv [1024, 1024] fp32 -> out [4, 2048, 1024] fp32.

#define BATCH 4
#define SEQ   2048
#define DM    1024
#define MTOT  (BATCH * SEQ)       // 8192

#define BM 128
#define BN 128
#define BK 16
#define NTH 256

// Scratch (no cudaMalloc allowed).
__device__ float g_Q[MTOT * DM];
__device__ float g_K[MTOT * DM];
__device__ float g_V[MTOT * DM];
__device__ float g_S[BATCH * SEQ * SEQ];

// ---------------------------------------------------------------------------
// helpers
// ---------------------------------------------------------------------------
__device__ __forceinline__ uint32_t smem_u32(const void* p) {
    return (uint32_t)__cvta_generic_to_shared(p);
}
__device__ __forceinline__ void cp16(uint32_t s, const void* g) {
    asm volatile("cp.async.cg.shared.global [%0], [%1], 16;" :: "r"(s), "l"(g));
}
#define CP_COMMIT() asm volatile("cp.async.commit_group;")
#define CP_WAIT0()  asm volatile("cp.async.wait_group 0;")

__device__ __forceinline__ uint32_t f2tf(float f) {
    uint32_t u;
    asm("cvt.rna.tf32.f32 %0, %1;" : "=r"(u) : "f"(f));
    return u;
}
__device__ __forceinline__ void mma8(float* c,
                                     uint32_t a0, uint32_t a1, uint32_t a2, uint32_t a3,
                                     uint32_t b0, uint32_t b1) {
    asm volatile(
        "mma.sync.aligned.m16n8k8.row.col.f32.tf32.tf32.f32 "
        "{%0,%1,%2,%3},{%4,%5,%6,%7},{%8,%9},{%0,%1,%2,%3};"
        : "+f"(c[0]), "+f"(c[1]), "+f"(c[2]), "+f"(c[3])
        : "r"(a0), "r"(a1), "r"(a2), "r"(a3), "r"(b0), "r"(b1));
}

// ---------------------------------------------------------------------------
// Kernel 1: QKV projection.  C = X[8192,1024] @ W[1024,1024], z in {Q,K,V}.
// A tile As[BM][BK+4]; B tile Bs[BK][BN+4] (row-major, k-major rows).
// ---------------------------------------------------------------------------
__global__ __launch_bounds__(NTH) void qkv_kernel(
    const float* __restrict__ x,
    const float* __restrict__ Wq,
    const float* __restrict__ Wk,
    const float* __restrict__ Wv)
{
    const float* W = (blockIdx.z == 0) ? Wq : (blockIdx.z == 1) ? Wk : Wv;
    float* C = (blockIdx.z == 0) ? g_Q : (blockIdx.z == 1) ? g_K : g_V;

    __shared__ __align__(16) float As[2][BM][BK + 4];
    __shared__ __align__(16) float Bs[2][BK][BN + 4];

    const int t    = threadIdx.x;
    const int lane = t & 31;
    const int warp = t >> 5;
    const int gid  = lane >> 2;
    const int tig  = lane & 3;
    const int wm   = warp & 1;   // 2 warp-rows of 64
    const int wn   = warp >> 1;  // 4 warp-cols of 32
    const int rowBase = blockIdx.y * BM;
    const int colBase = blockIdx.x * BN;

    float acc[4][4][4] = {};

    const int nIter = DM / BK;  // 64

    // prologue loads
    {
        #pragma unroll
        for (int i = 0; i < 2; i++) {
            int idx = t + i * 256;
            int r = idx >> 2, q = idx & 3;
            cp16(smem_u32(&As[0][r][q * 4]), &x[(size_t)(rowBase + r) * DM + q * 4]);
        }
        #pragma unroll
        for (int i = 0; i < 2; i++) {
            int idx = t + i * 256;
            int r = idx >> 5, q = idx & 31;
            cp16(smem_u32(&Bs[0][r][q * 4]), &W[(size_t)r * DM + colBase + q * 4]);
        }
        CP_COMMIT();
    }

    for (int it = 0; it < nIter; it++) {
        CP_WAIT0();
        __syncthreads();
        const int cur = it & 1;
        if (it + 1 < nIter) {
            const int k0 = (it + 1) * BK;
            #pragma unroll
            for (int i = 0; i < 2; i++) {
                int idx = t + i * 256;
                int r = idx >> 2, q = idx & 3;
                cp16(smem_u32(&As[cur ^ 1][r][q * 4]),
                     &x[(size_t)(rowBase + r) * DM + k0 + q * 4]);
            }
            #pragma unroll
            for (int i = 0; i < 2; i++) {
                int idx = t + i * 256;
                int r = idx >> 5, q = idx & 31;
                cp16(smem_u32(&Bs[cur ^ 1][r][q * 4]),
                     &W[(size_t)(k0 + r) * DM + colBase + q * 4]);
            }
            CP_COMMIT();
        }
        #pragma unroll
        for (int ks = 0; ks < 2; ks++) {
            const int kk = ks * 8;
            uint32_t af[4][4];
            #pragma unroll
            for (int mt = 0; mt < 4; mt++) {
                int r = wm * 64 + mt * 16 + gid;
                af[mt][0] = f2tf(As[cur][r][kk + tig]);
                af[mt][1] = f2tf(As[cur][r + 8][kk + tig]);
                af[mt][2] = f2tf(As[cur][r][kk + tig + 4]);
                af[mt][3] = f2tf(As[cur][r + 8][kk + tig + 4]);
            }
            #pragma unroll
            for (int nt = 0; nt < 4; nt++) {
                int c = wn * 32 + nt * 8 + gid;
                uint32_t b0 = f2tf(Bs[cur][kk + tig][c]);
                uint32_t b1 = f2tf(Bs[cur][kk + tig + 4][c]);
                #pragma unroll
                for (int mt = 0; mt < 4; mt++)
                    mma8(acc[mt][nt], af[mt][0], af[mt][1], af[mt][2], af[mt][3], b0, b1);
            }
        }
    }

    #pragma unroll
    for (int mt = 0; mt < 4; mt++) {
        int r = rowBase + wm * 64 + mt * 16 + gid;
        #pragma unroll
        for (int nt = 0; nt < 4; nt++) {
            int c = colBase + wn * 32 + nt * 8 + tig * 2;
            *(float2*)&C[(size_t)r * DM + c] = make_float2(acc[mt][nt][0], acc[mt][nt][1]);
            *(float2*)&C[(size_t)(r + 8) * DM + c] = make_float2(acc[mt][nt][2], acc[mt][nt][3]);
        }
    }
}

// ---------------------------------------------------------------------------
// Kernel 2: S[b] = (Q[b] @ K[b]^T) * scale for lower-triangle tiles only.
// B tile = K rows: Ks[BN][BK+4].
// ---------------------------------------------------------------------------
__global__ __launch_bounds__(NTH) void scores_kernel()
{
    const int by = blockIdx.y;
    const int bx = blockIdx.x;
    if (bx > by) return;
    const int b = blockIdx.z;

    const float* Qb = g_Q + (size_t)b * SEQ * DM;
    const float* Kb = g_K + (size_t)b * SEQ * DM;
    float*       Sb = g_S + (size_t)b * SEQ * SEQ;

    __shared__ __align__(16) float As[2][BM][BK + 4];
    __shared__ __align__(16) float Ks[2][BN][BK + 4];

    const int t    = threadIdx.x;
    const int lane = t & 31;
    const int warp = t >> 5;
    const int gid  = lane >> 2;
    const int tig  = lane & 3;
    const int wm   = warp & 1;
    const int wn   = warp >> 1;
    const int rowBase = by * BM;
    const int colBase = bx * BN;

    float acc[4][4][4] = {};
    const int nIter = DM / BK;

    {
        #pragma unroll
        for (int i = 0; i < 2; i++) {
            int idx = t + i * 256;
            int r = idx >> 2, q = idx & 3;
            cp16(smem_u32(&As[0][r][q * 4]), &Qb[(size_t)(rowBase + r) * DM + q * 4]);
            cp16(smem_u32(&Ks[0][r][q * 4]), &Kb[(size_t)(colBase + r) * DM + q * 4]);
        }
        CP_COMMIT();
    }

    for (int it = 0; it < nIter; it++) {
        CP_WAIT0();
        __syncthreads();
        const int cur = it & 1;
        if (it + 1 < nIter) {
            const int k0 = (it + 1) * BK;
            #pragma unroll
            for (int i = 0; i < 2; i++) {
                int idx = t + i * 256;
                int r = idx >> 2, q = idx & 3;
                cp16(smem_u32(&As[cur ^ 1][r][q * 4]),
                     &Qb[(size_t)(rowBase + r) * DM + k0 + q * 4]);
                cp16(smem_u32(&Ks[cur ^ 1][r][q * 4]),
                     &Kb[(size_t)(colBase + r) * DM + k0 + q * 4]);
            }
            CP_COMMIT();
        }
        #pragma unroll
        for (int ks = 0; ks < 2; ks++) {
            const int kk = ks * 8;
            uint32_t af[4][4];
            #pragma unroll
            for (int mt = 0; mt < 4; mt++) {
                int r = wm * 64 + mt * 16 + gid;
                af[mt][0] = f2tf(As[cur][r][kk + tig]);
                af[mt][1] = f2tf(As[cur][r + 8][kk + tig]);
                af[mt][2] = f2tf(As[cur][r][kk + tig + 4]);
                af[mt][3] = f2tf(As[cur][r + 8][kk + tig + 4]);
            }
            #pragma unroll
            for (int nt = 0; nt < 4; nt++) {
                int c = wn * 32 + nt * 8 + gid;
                uint32_t b0 = f2tf(Ks[cur][c][kk + tig]);
                uint32_t b1 = f2tf(Ks[cur][c][kk + tig + 4]);
                #pragma unroll
                for (int mt = 0; mt < 4; mt++)
                    mma8(acc[mt][nt], af[mt][0], af[mt][1], af[mt][2], af[mt][3], b0, b1);
            }
        }
    }

    const float scale = 0.03125f;  // 1/sqrt(1024)
    #pragma unroll
    for (int mt = 0; mt < 4; mt++) {
        int r = rowBase + wm * 64 + mt * 16 + gid;
        #pragma unroll
        for (int nt = 0; nt < 4; nt++) {
            int c = colBase + wn * 32 + nt * 8 + tig * 2;
            *(float2*)&Sb[(size_t)r * SEQ + c] =
                make_float2(acc[mt][nt][0] * scale, acc[mt][nt][1] * scale);
            *(float2*)&Sb[(size_t)(r + 8) * SEQ + c] =
                make_float2(acc[mt][nt][2] * scale, acc[mt][nt][3] * scale);
        }
    }
}

// ---------------------------------------------------------------------------
// Kernel 3: causal row softmax in place; zero-fill masked tail of each row.
// ---------------------------------------------------------------------------
__global__ __launch_bounds__(NTH) void softmax_kernel()
{
    __shared__ float buf[SEQ];
    __shared__ float red[8];

    const int row = blockIdx.x;
    const int b = row >> 11;
    const int q = row & (SEQ - 1);
    float* S = g_S + ((size_t)b * SEQ + q) * SEQ;
    const int L = q + 1;
    const int t = threadIdx.x;

    float mx = -3.402823e38f;
    for (int i = t; i < L; i += NTH) {
        float v = S[i];
        buf[i] = v;
        mx = fmaxf(mx, v);
    }
    #pragma unroll
    for (int o = 16; o; o >>= 1) mx = fmaxf(mx, __shfl_xor_sync(0xFFFFFFFFu, mx, o));
    if ((t & 31) == 0) red[t >> 5] = mx;
    __syncthreads();
    float m = red[0];
    #pragma unroll
    for (int i = 1; i < 8; i++) m = fmaxf(m, red[i]);
    __syncthreads();

    float sum = 0.0f;
    for (int i = t; i < L; i += NTH) {
        float e = __expf(buf[i] - m);
        buf[i] = e;
        sum += e;
    }
    #pragma unroll
    for (int o = 16; o; o >>= 1) sum += __shfl_xor_sync(0xFFFFFFFFu, sum, o);
    if ((t & 31) == 0) red[t >> 5] = sum;
    __syncthreads();
    float s = 0.0f;
    #pragma unroll
    for (int i = 0; i < 8; i++) s += red[i];
    const float inv = 1.0f / s;

    for (int i = t; i < SEQ; i += NTH)
        S[i] = (i < L) ? buf[i] * inv : 0.0f;
}

// ---------------------------------------------------------------------------
// Kernel 4: O[b] = P[b] @ V[b], K-loop truncated at the causal diagonal.
// ---------------------------------------------------------------------------
__global__ __launch_bounds__(NTH) void pv_kernel(float* __restrict__ out)
{
    const int by = blockIdx.y;   // query tile (0..15)
    const int bx = blockIdx.x;   // d tile (0..7)
    const int b  = blockIdx.z;

    const float* Pb = g_S + (size_t)b * SEQ * SEQ;
    const float* Vb = g_V + (size_t)b * SEQ * DM;
    float*       Ob = out + (size_t)b * SEQ * DM;

    __shared__ __align__(16) float As[2][BM][BK + 4];
    __shared__ __align__(16) float Bs[2][BK][BN + 4];

    const int t    = threadIdx.x;
    const int lane = t & 31;
    const int warp = t >> 5;
    const int gid  = lane >> 2;
    const int tig  = lane & 3;
    const int wm   = warp & 1;
    const int wn   = warp >> 1;
    const int rowBase = by * BM;
    const int colBase = bx * BN;

    float acc[4][4][4] = {};
    const int nIter = (by + 1) * (BM / BK);   // keys beyond (by+1)*128 have zero weight

    {
        #pragma unroll
        for (int i = 0; i < 2; i++) {
            int idx = t + i * 256;
            int r = idx >> 2, q = idx & 3;
            cp16(smem_u32(&As[0][r][q * 4]), &Pb[(size_t)(rowBase + r) * SEQ + q * 4]);
        }
        #pragma unroll
        for (int i = 0; i < 2; i++) {
            int idx = t + i * 256;
            int r = idx >> 5, q = idx & 31;
            cp16(smem_u32(&Bs[0][r][q * 4]), &Vb[(size_t)r * DM + colBase + q * 4]);
        }
        CP_COMMIT();
    }

    for (int it = 0; it < nIter; it++) {
        CP_WAIT0();
        __syncthreads();
        const int cur = it & 1;
        if (it + 1 < nIter) {
            const int k0 = (it + 1) * BK;
            #pragma unroll
            for (int i = 0; i < 2; i++) {
                int idx = t + i * 256;
                int r = idx >> 2, q = idx & 3;
                cp16(smem_u32(&As[cur ^ 1][r][q * 4]),
                     &Pb[(size_t)(rowBase + r) * SEQ + k0 + q * 4]);
            }
            #pragma unroll
            for (int i = 0; i < 2; i++) {
                int idx = t + i * 256;
                int r = idx >> 5, q = idx & 31;
                cp16(smem_u32(&Bs[cur ^ 1][r][q * 4]),
                     &Vb[(size_t)(k0 + r) * DM + colBase + q * 4]);
            }
            CP_COMMIT();
        }
        #pragma unroll
        for (int ks = 0; ks < 2; ks++) {
            const int kk = ks * 8;
            uint32_t af[4][4];
            #pragma unroll
            for (int mt = 0; mt < 4; mt++) {
                int r = wm * 64 + mt * 16 + gid;
                af[mt][0] = f2tf(As[cur][r][kk + tig]);
                af[mt][1] = f2tf(As[cur][r + 8][kk + tig]);
                af[mt][2] = f2tf(As[cur][r][kk + tig + 4]);
                af[mt][3] = f2tf(As[cur][r + 8][kk + tig + 4]);
            }
            #pragma unroll
            for (int nt = 0; nt < 4; nt++) {
                int c = wn * 32 + nt * 8 + gid;
                uint32_t b0 = f2tf(Bs[cur][kk + tig][c]);
                uint32_t b1 = f2tf(Bs[cur][kk + tig + 4][c]);
                #pragma unroll
                for (int mt = 0; mt < 4; mt++)
                    mma8(acc[mt][nt], af[mt][0], af[mt][1], af[mt][2], af[mt][3], b0, b1);
            }
        }
    }

    #pragma unroll
    for (int mt = 0; mt < 4; mt++) {
        int r = rowBase + wm * 64 + mt * 16 + gid;
        #pragma unroll
        for (int nt = 0; nt < 4; nt++) {
            int c = colBase + wn * 32 + nt * 8 + tig * 2;
            *(float2*)&Ob[(size_t)r * DM + c] = make_float2(acc[mt][nt][0], acc[mt][nt][1]);
            *(float2*)&Ob[(size_t)(r + 8) * DM + c] = make_float2(acc[mt][nt][2], acc[mt][nt][3]);
        }
    }
}

// ---------------------------------------------------------------------------
extern "C" void kernel_launch(void* const* d_in, const int* in_sizes, int n_in,
                              void* d_out, int out_size)
{
    const float* x  = (const float*)d_in[0];
    const float* Wq = (const float*)d_in[1];
    const float* Wk = (const float*)d_in[2];
    const float* Wv = (const float*)d_in[3];
    float* out = (float*)d_out;

    qkv_kernel<<<dim3(DM / BN, MTOT / BM, 3), NTH>>>(x, Wq, Wk, Wv);
    scores_kernel<<<dim3(SEQ / BN, SEQ / BM, BATCH), NTH>>>();
    softmax_kernel<<<MTOT, NTH>>>();
    pv_kernel<<<dim3(DM / BN, SEQ / BM, BATCH), NTH>>>(out);
}

// round 4
// speedup vs baseline: 3.1138x; 1.0901x over previous
#include <cuda_runtime.h>
#include <cstdint>

// x [4,2048,1024] fp32; Wq/Wk/Wv [1024,1024] fp32 -> out [4,2048,1024] fp32.

#define BATCH 4
#define SEQ   2048
#define DM    1024
#define MTOT  (BATCH * SEQ)   // 8192

#define BM 128
#define BN 128
#define NTH 256

// Scratch (no cudaMalloc allowed).
__device__ float g_X [MTOT * DM];          // rounded x, k-permuted
__device__ float g_Wt[3 * DM * DM];        // rounded W^T, k-permuted: [z][n][kperm]
__device__ float g_Q [MTOT * DM];          // rounded, d-permuted
__device__ float g_K [MTOT * DM];          // rounded, d-permuted
__device__ float g_V [MTOT * DM];          // rounded, linear
__device__ float g_Vt[BATCH * DM * SEQ];   // V^T, s-permuted: [d][sperm]
__device__ float g_S [BATCH * SEQ * SEQ];  // scores / P, col(s)-permuted

// Permutation within a 16-group: value at position p came from offset
// (p%4)*4 + p/4.  Self-inverse.
__device__ __forceinline__ int porig(int i) {
    return (i & ~15) | ((i & 3) << 2) | ((i >> 2) & 3);
}

// ---------------------------------------------------------------------------
// PTX helpers
// ---------------------------------------------------------------------------
__device__ __forceinline__ uint32_t smem_u32(const void* p) {
    return (uint32_t)__cvta_generic_to_shared(p);
}
__device__ __forceinline__ void cp16(uint32_t s, const void* g) {
    asm volatile("cp.async.cg.shared.global [%0], [%1], 16;" :: "r"(s), "l"(g));
}
#define CP_COMMIT() asm volatile("cp.async.commit_group;")

__device__ __forceinline__ uint32_t f2tf(float f) {
    uint32_t u;
    asm("cvt.rna.tf32.f32 %0, %1;" : "=r"(u) : "f"(f));
    return u;
}
__device__ __forceinline__ float rnd_tf32(float f) { return __uint_as_float(f2tf(f)); }

__device__ __forceinline__ void mma8(float* c,
                                     float a0, float a1, float a2, float a3,
                                     float b0, float b1) {
    asm volatile(
        "mma.sync.aligned.m16n8k8.row.col.f32.tf32.tf32.f32 "
        "{%0,%1,%2,%3},{%4,%5,%6,%7},{%8,%9},{%0,%1,%2,%3};"
        : "+f"(c[0]), "+f"(c[1]), "+f"(c[2]), "+f"(c[3])
        : "r"(__float_as_uint(a0)), "r"(__float_as_uint(a1)),
          "r"(__float_as_uint(a2)), "r"(__float_as_uint(a3)),
          "r"(__float_as_uint(b0)), "r"(__float_as_uint(b1)));
}

// ---------------------------------------------------------------------------
// prep kernels
// ---------------------------------------------------------------------------
__global__ void prep_x_kernel(const float* __restrict__ x) {
    int i = blockIdx.x * blockDim.x + threadIdx.x;   // one 16-group per thread
    float4 in[4];
    #pragma unroll
    for (int j = 0; j < 4; j++) in[j] = ((const float4*)x)[i * 4 + j];
    const float* f = (const float*)in;
    #pragma unroll
    for (int u = 0; u < 4; u++) {
        float4 o = make_float4(rnd_tf32(f[u]), rnd_tf32(f[4 + u]),
                               rnd_tf32(f[8 + u]), rnd_tf32(f[12 + u]));
        ((float4*)g_X)[i * 4 + u] = o;
    }
}

// W[k][n] -> Wt[n][kperm], rounded.
__global__ void prep_w_kernel(const float* __restrict__ Wq,
                              const float* __restrict__ Wk,
                              const float* __restrict__ Wv) {
    __shared__ float tile[32][33];
    const float* W = (blockIdx.z == 0) ? Wq : (blockIdx.z == 1) ? Wk : Wv;
    float* Wt = g_Wt + (size_t)blockIdx.z * DM * DM;
    int nb = blockIdx.x * 32, kb = blockIdx.y * 32;
    int tx = threadIdx.x, ty = threadIdx.y;
    #pragma unroll
    for (int j = 0; j < 4; j++)
        tile[ty + 8 * j][tx] = W[(size_t)(kb + ty + 8 * j) * DM + nb + tx];
    __syncthreads();
    #pragma unroll
    for (int j = 0; j < 4; j++) {
        int n = ty + 8 * j;
        int ko = (tx & ~15) | ((tx & 3) << 2) | ((tx >> 2) & 3);
        Wt[(size_t)(nb + n) * DM + kb + tx] = rnd_tf32(tile[ko][n]);
    }
}

// V[s][d] (rounded) -> Vt[d][sperm].
__global__ void transpose_v_kernel() {
    __shared__ float tile[32][33];
    int b = blockIdx.z;
    const float* V = g_V + (size_t)b * SEQ * DM;
    float* Vt = g_Vt + (size_t)b * DM * SEQ;
    int db = blockIdx.x * 32, sb = blockIdx.y * 32;
    int tx = threadIdx.x, ty = threadIdx.y;
    #pragma unroll
    for (int j = 0; j < 4; j++)
        tile[ty + 8 * j][tx] = V[(size_t)(sb + ty + 8 * j) * DM + db + tx];
    __syncthreads();
    #pragma unroll
    for (int j = 0; j < 4; j++) {
        int d = ty + 8 * j;
        int so = (tx & ~15) | ((tx & 3) << 2) | ((tx >> 2) & 3);
        Vt[(size_t)(db + d) * SEQ + sb + tx] = tile[so][d];
    }
}

// ---------------------------------------------------------------------------
// Unified tf32 mma GEMM: C[128,128] = A[m][kperm] @ B[n][kperm]^T.
// mode 0: round + perm cols (Q,K).   mode 1: round + linear (V).
// mode 2: scale + perm cols + causal tile skip (scores).
// mode 3: linear, K truncated at diagonal (PV / output).
// ---------------------------------------------------------------------------
#define SMEM_DYN 35840

__global__ __launch_bounds__(NTH) void gemm_kernel(
    const float* __restrict__ Ag, const float* __restrict__ Bg, float* __restrict__ Cg,
    int ldA, int ldB, int ldC,
    long long strideAz, long long strideBz, long long strideCz,
    int kGroupsFull, float scale, int mode)
{
    const int by = blockIdx.y, bx = blockIdx.x, bz = blockIdx.z;
    if (mode == 2 && bx > by) return;
    const int kG = (mode == 3) ? (by + 1) * 8 : kGroupsFull;

    const float* A = Ag + (size_t)bz * strideAz + (size_t)by * BM * ldA;
    const float* B = Bg + (size_t)bz * strideBz + (size_t)bx * BN * ldB;
    float*       C = Cg + (size_t)bz * strideCz + (size_t)by * BM * ldC + bx * BN;

    extern __shared__ float dsm[];
    float* As = dsm;                 // [2][128][16]
    float* Bs = dsm + 2 * 128 * 16;  // [2][128][16]

    const int t    = threadIdx.x;
    const int lane = t & 31;
    const int warp = t >> 5;
    const int gid  = lane >> 2;
    const int tig  = lane & 3;
    const int wm   = warp & 1;       // 2 warp-rows of 64
    const int wn   = warp >> 1;      // 4 warp-cols of 32

    float acc[4][4][4] = {};

    auto load_group = [&](int g, int buf) {
        #pragma unroll
        for (int j = 0; j < 2; j++) {
            int idx = t + j * NTH;                // 0..511
            int r = idx >> 2, q = idx & 3;
            cp16(smem_u32(As + buf * 2048 + r * 16 + q * 4),
                 A + (size_t)r * ldA + g * 16 + q * 4);
        }
        #pragma unroll
        for (int j = 0; j < 2; j++) {
            int idx = t + j * NTH;
            int r = idx >> 2, q = idx & 3;
            cp16(smem_u32(Bs + buf * 2048 + r * 16 + q * 4),
                 B + (size_t)r * ldB + g * 16 + q * 4);
        }
        CP_COMMIT();
    };

    load_group(0, 0);

    for (int g = 0; g < kG; g++) {
        const int buf = g & 1;
        if (g + 1 < kG) {
            load_group(g + 1, buf ^ 1);
            asm volatile("cp.async.wait_group 1;");
        } else {
            asm volatile("cp.async.wait_group 0;");
        }
        __syncthreads();

        const float* Ab = As + buf * 2048;
        const float* Bb = Bs + buf * 2048;
        float4 fa[4], fa2[4];
        #pragma unroll
        for (int mt = 0; mt < 4; mt++) {
            int r = wm * 64 + mt * 16 + gid;
            fa[mt]  = *(const float4*)(Ab + r * 16 + tig * 4);
            fa2[mt] = *(const float4*)(Ab + (r + 8) * 16 + tig * 4);
        }
        #pragma unroll
        for (int nt = 0; nt < 4; nt++) {
            int c = wn * 32 + nt * 8 + gid;
            float4 fb = *(const float4*)(Bb + c * 16 + tig * 4);
            #pragma unroll
            for (int mt = 0; mt < 4; mt++) {
                mma8(acc[mt][nt], fa[mt].x, fa2[mt].x, fa[mt].y, fa2[mt].y, fb.x, fb.y);
                mma8(acc[mt][nt], fa[mt].z, fa2[mt].z, fa[mt].w, fa2[mt].w, fb.z, fb.w);
            }
        }
        __syncthreads();
    }

    // Epilogue: two 64-col halves through a smem stage.
    const bool doRound = (mode == 0) || (mode == 1);
    const bool permOut = (mode == 0) || (mode == 2);
    float (*stage)[69] = (float(*)[69])dsm;      // 128 x 69 = 35.3KB

    #pragma unroll
    for (int h = 0; h < 2; h++) {
        __syncthreads();
        if ((wn >> 1) == h) {
            #pragma unroll
            for (int mt = 0; mt < 4; mt++) {
                int r1 = wm * 64 + mt * 16 + gid;
                #pragma unroll
                for (int nt = 0; nt < 4; nt++) {
                    int cl = (wn & 1) * 32 + nt * 8 + tig * 2;
                    float v0 = acc[mt][nt][0] * scale, v1 = acc[mt][nt][1] * scale;
                    float v2 = acc[mt][nt][2] * scale, v3 = acc[mt][nt][3] * scale;
                    if (doRound) {
                        v0 = rnd_tf32(v0); v1 = rnd_tf32(v1);
                        v2 = rnd_tf32(v2); v3 = rnd_tf32(v3);
                    }
                    stage[r1][cl] = v0;     stage[r1][cl + 1] = v1;
                    stage[r1 + 8][cl] = v2; stage[r1 + 8][cl + 1] = v3;
                }
            }
        }
        __syncthreads();
        {
            const int rr  = t & 127;
            const int sub = t >> 7;            // 0..1 -> 32-col subhalf
            float* dst = C + (size_t)rr * ldC + h * 64 + sub * 32;
            const float* src = stage[rr] + sub * 32;
            if (permOut) {
                #pragma unroll
                for (int gi = 0; gi < 2; gi++) {
                    #pragma unroll
                    for (int u = 0; u < 4; u++) {
                        float4 v = make_float4(src[gi * 16 + u],     src[gi * 16 + u + 4],
                                               src[gi * 16 + u + 8], src[gi * 16 + u + 12]);
                        *(float4*)(dst + gi * 16 + u * 4) = v;
                    }
                }
            } else {
                #pragma unroll
                for (int u = 0; u < 8; u++) {
                    float4 v = make_float4(src[u * 4], src[u * 4 + 1],
                                           src[u * 4 + 2], src[u * 4 + 3]);
                    *(float4*)(dst + u * 4) = v;
                }
            }
        }
    }
}

// ---------------------------------------------------------------------------
// Causal softmax over permuted rows; rounds P to tf32; zero-fills invalid.
// ---------------------------------------------------------------------------
__global__ __launch_bounds__(NTH) void softmax_kernel()
{
    __shared__ float buf[SEQ];
    __shared__ float red[8];

    const int row = blockIdx.x;
    const int b = row >> 11;
    const int q = row & (SEQ - 1);
    float* S = g_S + ((size_t)b * SEQ + q) * SEQ;
    const int L = q + 1;
    const int Lcap = (L + 15) & ~15;       // covers the boundary group
    const int t = threadIdx.x;

    float mx = -3.402823e38f;
    for (int i = t; i < Lcap; i += NTH) {
        float v = S[i];
        buf[i] = v;
        if (porig(i) < L) mx = fmaxf(mx, v);
    }
    #pragma unroll
    for (int o = 16; o; o >>= 1) mx = fmaxf(mx, __shfl_xor_sync(0xFFFFFFFFu, mx, o));
    if ((t & 31) == 0) red[t >> 5] = mx;
    __syncthreads();
    float m = red[0];
    #pragma unroll
    for (int i = 1; i < 8; i++) m = fmaxf(m, red[i]);
    __syncthreads();

    float sum = 0.0f;
    for (int i = t; i < Lcap; i += NTH) {
        if (porig(i) < L) {
            float e = __expf(buf[i] - m);
            buf[i] = e;
            sum += e;
        }
    }
    #pragma unroll
    for (int o = 16; o; o >>= 1) sum += __shfl_xor_sync(0xFFFFFFFFu, sum, o);
    if ((t & 31) == 0) red[t >> 5] = sum;
    __syncthreads();
    float s = 0.0f;
    #pragma unroll
    for (int i = 0; i < 8; i++) s += red[i];
    const float inv = 1.0f / s;

    for (int i = t; i < SEQ; i += NTH) {
        float v = 0.0f;
        if (i < Lcap && porig(i) < L) v = rnd_tf32(buf[i] * inv);
        S[i] = v;
    }
}

// ---------------------------------------------------------------------------
extern "C" void kernel_launch(void* const* d_in, const int* in_sizes, int n_in,
                              void* d_out, int out_size)
{
    const float* x  = (const float*)d_in[0];
    const float* Wq = (const float*)d_in[1];
    const float* Wk = (const float*)d_in[2];
    const float* Wv = (const float*)d_in[3];
    float* out = (float*)d_out;

    cudaFuncSetAttribute(gemm_kernel, cudaFuncAttributeMaxDynamicSharedMemorySize, SMEM_DYN);

    float *pX, *pWt, *pQ, *pK, *pV, *pVt, *pS;
    cudaGetSymbolAddress((void**)&pX,  g_X);
    cudaGetSymbolAddress((void**)&pWt, g_Wt);
    cudaGetSymbolAddress((void**)&pQ,  g_Q);
    cudaGetSymbolAddress((void**)&pK,  g_K);
    cudaGetSymbolAddress((void**)&pV,  g_V);
    cudaGetSymbolAddress((void**)&pVt, g_Vt);
    cudaGetSymbolAddress((void**)&pS,  g_S);

    prep_x_kernel<<<2048, 256>>>(x);
    prep_w_kernel<<<dim3(32, 32, 3), dim3(32, 8)>>>(Wq, Wk, Wv);

    // Q, K: round + permuted cols.  V: round + linear.
    gemm_kernel<<<dim3(8, 64, 1), NTH, SMEM_DYN>>>(
        pX, pWt + 0 * (size_t)DM * DM, pQ, DM, DM, DM, 0, 0, 0, 64, 1.0f, 0);
    gemm_kernel<<<dim3(8, 64, 1), NTH, SMEM_DYN>>>(
        pX, pWt + 1 * (size_t)DM * DM, pK, DM, DM, DM, 0, 0, 0, 64, 1.0f, 0);
    gemm_kernel<<<dim3(8, 64, 1), NTH, SMEM_DYN>>>(
        pX, pWt + 2 * (size_t)DM * DM, pV, DM, DM, DM, 0, 0, 0, 64, 1.0f, 1);

    transpose_v_kernel<<<dim3(32, 64, BATCH), dim3(32, 8)>>>();

    // Scores: S = (Q @ K^T) * scale, lower tiles only, permuted cols.
    gemm_kernel<<<dim3(16, 16, BATCH), NTH, SMEM_DYN>>>(
        pQ, pK, pS, DM, DM, SEQ,
        (long long)SEQ * DM, (long long)SEQ * DM, (long long)SEQ * SEQ,
        64, 0.03125f, 2);

    softmax_kernel<<<MTOT, NTH>>>();

    // PV: O = P @ Vt^T, K truncated at diagonal, linear output.
    gemm_kernel<<<dim3(8, 16, BATCH), NTH, SMEM_DYN>>>(
        pS, pVt, out, SEQ, SEQ, DM,
        (long long)SEQ * SEQ, (long long)DM * SEQ, (long long)SEQ * DM,
        128, 1.0f, 3);
}